// round 6
// baseline (speedup 1.0000x reference)
#include <cuda_runtime.h>

// Problem constants
#define Bc 4096
#define Tc 256
#define I1c 38
#define H1c 50
#define H2c 15
#define NCc 14

// Tiling
#define NB    32           // batch elems per CTA
#define NTH   576          // 18 warps: 520 workers + pad + 1 prefetch warp
#define NWORK 520          // 65 units x 8 colgroups (4 batch each)
#define NU    65           // 50 L1 units + 15 L2 units
#define KL    88           // padded dot length (38+50); L2 window base 38 + zero pad
#define KL2   65           // real dot length for L2 (50+15)
#define KH    44           // KL/2 (k-pairs)
#define VP    32           // value-vector pitch (floats) = 128 B
#define VROWS 128          // rows: [0,38)=x, [38,88)=h1, [88,103)=h2, rest zero
#define VSZ   (VROWS*VP)   // 4096 floats per buffer

// Weight table: ulonglong2 wq[((k2*4)+g)*NU + u] = {(w_{2k2},w_{2k2}), (w_{2k2+1},w_{2k2+1})}
#define WQ_N      (KH*4*NU)            // 11440 ulonglong2
#define SM_V_OFF  (WQ_N*16)            // 183040 B
#define SMEM_BYTES (SM_V_OFF + 2*VSZ*4)   // 215808 B

typedef unsigned long long u64t;

__device__ __forceinline__ u64t pk2(float a, float b){
    u64t d; asm("mov.b64 %0, {%1, %2};" : "=l"(d) : "f"(a), "f"(b)); return d;
}
__device__ __forceinline__ void up2(u64t d, float& a, float& b){
    asm("mov.b64 {%0, %1}, %2;" : "=f"(a), "=f"(b) : "l"(d));
}
__device__ __forceinline__ void fma2(u64t& d, u64t a, u64t b){
    asm("fma.rn.f32x2 %0, %1, %2, %0;" : "+l"(d) : "l"(a), "l"(b));
}

__device__ __forceinline__ float sigf(float x){
    float e = __expf(-x);
    return __fdividef(1.0f, 1.0f + e);
}
__device__ __forceinline__ float tanh_(float x){
    float a = fabsf(x);
    float e = __expf(-2.0f * a);
    float r = __fdividef(1.0f - e, 1.0f + e);
    return copysignf(r, x);
}

// Weight fetch for unified row space. u<50: L1 unit, window [x|h1], base 0.
// u>=50: L2 unit r=u-50, window [h1|h2|pad], base 38 applied at read time.
__device__ __forceinline__ float wfetch(int u, int g, int k,
    const float* __restrict__ w_ih1, const float* __restrict__ w_hh1,
    const float* __restrict__ w_ih2, const float* __restrict__ w_hh2)
{
    if (u < 50){
        int row = g * H1c + u;
        return (k < I1c) ? w_ih1[row*I1c + k] : w_hh1[row*H1c + (k - I1c)];
    } else {
        int r = u - 50, row = g * H2c + r;
        if (k < H1c)      return w_ih2[row*H1c + k];
        else if (k < KL2) return w_hh2[row*H2c + (k - H1c)];
        return 0.0f;
    }
}

__global__ __launch_bounds__(NTH, 1)
void lstm_persist_kernel(const float* __restrict__ x,
                         const float* __restrict__ w_ih1, const float* __restrict__ w_hh1,
                         const float* __restrict__ b_ih1, const float* __restrict__ b_hh1,
                         const float* __restrict__ w_ih2, const float* __restrict__ w_hh2,
                         const float* __restrict__ b_ih2, const float* __restrict__ b_hh2,
                         const float* __restrict__ w_fc,  const float* __restrict__ b_fc,
                         float* __restrict__ out)
{
    extern __shared__ float sm[];
    ulonglong2* wq  = reinterpret_cast<ulonglong2*>(sm);
    float* vbuf = sm + SM_V_OFF / 4;

    const int tid = threadIdx.x;
    const int b0  = blockIdx.x * NB;

    // ---- Build paired duplicated weight table ----
    for (int idx = tid; idx < WQ_N; idx += NTH){
        int u  = idx % NU;
        int t2 = idx / NU;         // k2*4 + g
        int g  = t2 & 3, k2 = t2 >> 2;
        float w0 = wfetch(u, g, 2*k2,     w_ih1, w_hh1, w_ih2, w_hh2);
        float w1 = wfetch(u, g, 2*k2 + 1, w_ih1, w_hh1, w_ih2, w_hh2);
        ulonglong2 e; e.x = pk2(w0, w0); e.y = pk2(w1, w1);
        wq[idx] = e;
    }

    // ---- Zero both v buffers (incl. pad rows), then load x(0) ----
    for (int idx = tid; idx < 2*VSZ; idx += NTH) vbuf[idx] = 0.0f;
    __syncthreads();
    for (int idx = tid; idx < NB*I1c; idx += NTH){
        int nb = idx / I1c, i = idx % I1c;
        vbuf[i*VP + nb] = x[((size_t)(b0 + nb) * Tc) * I1c + i];
    }

    // Roles: tid < 520 -> worker (u, cg); tid in [544,576) -> prefetch lane
    const int u  = tid >> 3;       // unit group 0..64 (valid for tid<520)
    const int cg = tid & 7;        // 4-batch colgroup
    const bool isL1 = (u < 50);
    const bool work = (tid < NWORK);

    float bias[4];
    if (work){
        if (isL1){
            #pragma unroll
            for (int g = 0; g < 4; g++) bias[g] = b_ih1[g*H1c + u] + b_hh1[g*H1c + u];
        } else {
            int r = u - 50;
            #pragma unroll
            for (int g = 0; g < 4; g++) bias[g] = b_ih2[g*H2c + r] + b_hh2[g*H2c + r];
        }
    }

    float cst[4];
    #pragma unroll
    for (int s = 0; s < 4; s++) cst[s] = 0.0f;

    const int base = isL1 ? 0 : I1c;
    const int hrow = isL1 ? (I1c + u) : (88 + (u - 50));
    __syncthreads();

    // Iter t: L1 computes step t (x(t), h1(t-1)); L2 computes step t-1
    // (h1(t-1), h2(t-2)). Writes go to vn; single barrier per iteration.
    for (int t = 0; t <= Tc; t++){
        float* vc = vbuf + (t & 1) * VSZ;
        float* vn = vbuf + ((t + 1) & 1) * VSZ;

        if (work && (isL1 ? (t < Tc) : true)){
            u64t a00, a01, a10, a11, a20, a21, a30, a31;
            a00 = a01 = pk2(bias[0], bias[0]);
            a10 = a11 = pk2(bias[1], bias[1]);
            a20 = a21 = pk2(bias[2], bias[2]);
            a30 = a31 = pk2(bias[3], bias[3]);

            // v row k lives at vc + (base+k)*VP + cg*4 floats -> ulonglong2 idx k*8+cg
            const ulonglong2* vr = reinterpret_cast<const ulonglong2*>(vc + base*VP) + cg;
            const ulonglong2* wr = wq + u;
            #pragma unroll 2
            for (int k2 = 0; k2 < KH; k2++){
                ulonglong2 v0 = vr[(2*k2    )*8];
                ulonglong2 v1 = vr[(2*k2 + 1)*8];
                ulonglong2 w0 = wr[(k2*4 + 0)*NU];
                ulonglong2 w1 = wr[(k2*4 + 1)*NU];
                ulonglong2 w2 = wr[(k2*4 + 2)*NU];
                ulonglong2 w3 = wr[(k2*4 + 3)*NU];
                fma2(a00, w0.x, v0.x); fma2(a01, w0.x, v0.y);
                fma2(a10, w1.x, v0.x); fma2(a11, w1.x, v0.y);
                fma2(a20, w2.x, v0.x); fma2(a21, w2.x, v0.y);
                fma2(a30, w3.x, v0.x); fma2(a31, w3.x, v0.y);
                fma2(a00, w0.y, v1.x); fma2(a01, w0.y, v1.y);
                fma2(a10, w1.y, v1.x); fma2(a11, w1.y, v1.y);
                fma2(a20, w2.y, v1.x); fma2(a21, w2.y, v1.y);
                fma2(a30, w3.y, v1.x); fma2(a31, w3.y, v1.y);
            }

            if (isL1 || t >= 1){       // L2's step t-1 exists only for t>=1
                float i0,i1,i2,i3, f0,f1,f2,f3, g0,g1,g2,g3, o0,o1,o2,o3;
                up2(a00, i0, i1); up2(a01, i2, i3);
                up2(a10, f0, f1); up2(a11, f2, f3);
                up2(a20, g0, g1); up2(a21, g2, g3);
                up2(a30, o0, o1); up2(a31, o2, o3);
                float c0 = fmaf(sigf(f0), cst[0], sigf(i0)*tanh_(g0));
                float c1 = fmaf(sigf(f1), cst[1], sigf(i1)*tanh_(g1));
                float c2 = fmaf(sigf(f2), cst[2], sigf(i2)*tanh_(g2));
                float c3 = fmaf(sigf(f3), cst[3], sigf(i3)*tanh_(g3));
                cst[0] = c0; cst[1] = c1; cst[2] = c2; cst[3] = c3;
                float4 hv;
                hv.x = sigf(o0)*tanh_(c0);
                hv.y = sigf(o1)*tanh_(c1);
                hv.z = sigf(o2)*tanh_(c2);
                hv.w = sigf(o3)*tanh_(c3);
                *reinterpret_cast<float4*>(vn + hrow*VP + cg*4) = hv;
            }
        } else if (tid >= 544){
            // ---- Prefetch warp: x(t+1) -> vn rows [0,38), column j ----
            int j = tid - 544;         // batch lane 0..31
            if (t + 1 < Tc){
                const float* xs = x + ((size_t)(b0 + j) * Tc + (t + 1)) * I1c;
                float* xd = vn + j;
                #pragma unroll
                for (int i = 0; i < I1c; i++) xd[i*VP] = __ldcg(xs + i);
            }
        }
        __syncthreads();
    }

    // ---- FC head: final h2 lives in vbuf[1] rows 88..102 ----
    const float* h2f = vbuf + VSZ + 88*VP;
    for (int q = tid; q < NB*NCc; q += NTH){
        int nb = q / NCc, cls = q % NCc;
        float s = b_fc[cls];
        #pragma unroll
        for (int h = 0; h < H2c; h++)
            s = fmaf(w_fc[cls*H2c + h], h2f[h*VP + nb], s);
        out[(size_t)(b0 + nb)*NCc + cls] = s;
    }
}

extern "C" void kernel_launch(void* const* d_in, const int* in_sizes, int n_in,
                              void* d_out, int out_size)
{
    const float* x     = (const float*)d_in[0];
    const float* w_ih1 = (const float*)d_in[1];
    const float* w_hh1 = (const float*)d_in[2];
    const float* b_ih1 = (const float*)d_in[3];
    const float* b_hh1 = (const float*)d_in[4];
    const float* w_ih2 = (const float*)d_in[5];
    const float* w_hh2 = (const float*)d_in[6];
    const float* b_ih2 = (const float*)d_in[7];
    const float* b_hh2 = (const float*)d_in[8];
    const float* w_fc  = (const float*)d_in[9];
    const float* b_fc  = (const float*)d_in[10];
    float* out = (float*)d_out;

    cudaFuncSetAttribute(lstm_persist_kernel,
                         cudaFuncAttributeMaxDynamicSharedMemorySize, SMEM_BYTES);

    const int grid = Bc / NB;   // 128 CTAs -> one wave
    lstm_persist_kernel<<<grid, NTH, SMEM_BYTES>>>(
        x, w_ih1, w_hh1, b_ih1, b_hh1,
        w_ih2, w_hh2, b_ih2, b_hh2, w_fc, b_fc, out);
}

// round 8
// speedup vs baseline: 1.1721x; 1.1721x over previous
#include <cuda_runtime.h>

// Problem constants
#define Bc 4096
#define Tc 256
#define I1c 38
#define H1c 50
#define H2c 15
#define NCc 14

// Tiling
#define NB    32           // batch per CTA
#define NTH   576          // 18 warps
#define NWORK 520          // 65 units x 4 cg x 2 khalf
#define NU    65           // 50 L1 + 15 L2 unit-groups
#define NUP   66           // padded unit pitch (bank layout)
#define KL    88           // padded dot length (L2 zero-padded)
#define KL2   65
#define VPF   36           // v row pitch in floats (144 B) -> conflict-free kh split
#define VROWS 128          // [0,38)=x, [38,88)=h1, [88,103)=h2, rest zero
#define VSZ   (VROWS*VPF)  // 4608 floats per buffer

// Weight table: ulonglong2 wq[(k*2+gp)*NUP + u]
//   gp=0 -> {(wi,wi),(wf,wf)}, gp=1 -> {(wg,wg),(wo,wo)}
#define WQ_N          (KL*2*NUP)          // 11616 ulonglong2 = 185856 B
#define SM_V_BYTE     (WQ_N*16)
#define SM_STAGE_BYTE (SM_V_BYTE + 2*VSZ*4)   // 222720
#define STAGE_PITCH   41
#define SMEM_BYTES    (SM_STAGE_BYTE + 32*STAGE_PITCH*4)  // 227968 B

typedef unsigned long long u64t;

__device__ __forceinline__ u64t pk2(float a, float b){
    u64t d; asm("mov.b64 %0, {%1, %2};" : "=l"(d) : "f"(a), "f"(b)); return d;
}
__device__ __forceinline__ void up2(u64t d, float& a, float& b){
    asm("mov.b64 {%0, %1}, %2;" : "=f"(a), "=f"(b) : "l"(d));
}
__device__ __forceinline__ void fma2(u64t& d, u64t a, u64t b){
    asm("fma.rn.f32x2 %0, %1, %2, %0;" : "+l"(d) : "l"(a), "l"(b));
}
__device__ __forceinline__ u64t add2(u64t a, u64t b){
    u64t d; asm("add.rn.f32x2 %0, %1, %2;" : "=l"(d) : "l"(a), "l"(b)); return d;
}

__device__ __forceinline__ float sigf(float x){
    float e = __expf(-x);
    return __fdividef(1.0f, 1.0f + e);
}
__device__ __forceinline__ float tanh_(float x){
    float a = fabsf(x);
    float e = __expf(-2.0f * a);
    float r = __fdividef(1.0f - e, 1.0f + e);
    return copysignf(r, x);
}

// Unified-row weight fetch. u<50: L1 unit (window [x|h1], base 0).
// u>=50 (<65): L2 unit r (window [h1|h2|pad], base 38). u==65: pad column.
__device__ __forceinline__ float wfetch(int u, int g, int k,
    const float* __restrict__ w_ih1, const float* __restrict__ w_hh1,
    const float* __restrict__ w_ih2, const float* __restrict__ w_hh2)
{
    if (u < 50){
        int row = g * H1c + u;
        return (k < I1c) ? w_ih1[row*I1c + k] : w_hh1[row*H1c + (k - I1c)];
    } else if (u < NU){
        int r = u - 50, row = g * H2c + r;
        if (k < H1c)      return w_ih2[row*H1c + k];
        else if (k < KL2) return w_hh2[row*H2c + (k - H1c)];
    }
    return 0.0f;
}

__global__ __launch_bounds__(NTH, 1)
void lstm_persist_kernel(const float* __restrict__ x,
                         const float* __restrict__ w_ih1, const float* __restrict__ w_hh1,
                         const float* __restrict__ b_ih1, const float* __restrict__ b_hh1,
                         const float* __restrict__ w_ih2, const float* __restrict__ w_hh2,
                         const float* __restrict__ b_ih2, const float* __restrict__ b_hh2,
                         const float* __restrict__ w_fc,  const float* __restrict__ b_fc,
                         float* __restrict__ out)
{
    extern __shared__ char smc[];
    ulonglong2* wq   = reinterpret_cast<ulonglong2*>(smc);
    float*      vbuf = reinterpret_cast<float*>(smc + SM_V_BYTE);
    float*      stg  = reinterpret_cast<float*>(smc + SM_STAGE_BYTE);

    const int tid = threadIdx.x;
    const int b0  = blockIdx.x * NB;

    // ---- Build gate-packed duplicated weight table ----
    for (int idx = tid; idx < WQ_N; idx += NTH){
        int u  = idx % NUP;
        int t2 = idx / NUP;          // k*2 + gp
        int gp = t2 & 1, k = t2 >> 1;
        float wa = wfetch(u, gp*2,     k, w_ih1, w_hh1, w_ih2, w_hh2);
        float wb = wfetch(u, gp*2 + 1, k, w_ih1, w_hh1, w_ih2, w_hh2);
        ulonglong2 e; e.x = pk2(wa, wa); e.y = pk2(wb, wb);
        wq[idx] = e;
    }

    // ---- Zero both v buffers (incl. pad rows), then load x(0) ----
    for (int idx = tid; idx < 2*VSZ; idx += NTH) vbuf[idx] = 0.0f;
    __syncthreads();
    for (int idx = tid; idx < NB*I1c; idx += NTH){
        int nb = idx / I1c, i = idx % I1c;
        vbuf[i*VPF + nb] = x[((size_t)(b0 + nb) * Tc) * I1c + i];
    }

    // Worker roles: u = tid>>3, cg = (tid>>1)&3 (8 batch), kh = tid&1 (k parity)
    const int u  = tid >> 3;
    const int cg = (tid >> 1) & 3;
    const int kh = tid & 1;
    const bool isL1 = (u < 50);
    const bool work = (tid < NWORK);
    // Shuffle partner is strictly lane^1 (same unit, same branch conditions):
    // use the exact pair mask so mixed-unit warps can never deadlock.
    const unsigned pmask = 0x3u << ((tid & 31) & ~1);

    float bI=0, bF=0, bG=0, bO=0;
    if (work && kh == 0){   // only kh=0 carries bias (butterfly would double it)
        if (isL1){
            bI = b_ih1[0*H1c+u] + b_hh1[0*H1c+u];
            bF = b_ih1[1*H1c+u] + b_hh1[1*H1c+u];
            bG = b_ih1[2*H1c+u] + b_hh1[2*H1c+u];
            bO = b_ih1[3*H1c+u] + b_hh1[3*H1c+u];
        } else {
            int r = u - 50;
            bI = b_ih2[0*H2c+r] + b_hh2[0*H2c+r];
            bF = b_ih2[1*H2c+r] + b_hh2[1*H2c+r];
            bG = b_ih2[2*H2c+r] + b_hh2[2*H2c+r];
            bO = b_ih2[3*H2c+r] + b_hh2[3*H2c+r];
        }
    }

    float cst[4];   // this thread's 4 batches: cg*8 + kh*4 + {0..3}
    #pragma unroll
    for (int s = 0; s < 4; s++) cst[s] = 0.0f;

    const int base = isL1 ? 0 : I1c;
    const int hrow = isL1 ? (I1c + u) : (88 + (u - 50));
    __syncthreads();

    // Iter t: L1 computes step t (x(t), h1(t-1)); L2 computes step t-1.
    for (int t = 0; t <= Tc; t++){
        float* vc = vbuf + (t & 1) * VSZ;
        float* vn = vbuf + ((t + 1) & 1) * VSZ;

        if (work){
            u64t aI[4], aF[4], aG[4], aO[4];
            #pragma unroll
            for (int p = 0; p < 4; p++){
                aI[p] = pk2(bI,bI); aF[p] = pk2(bF,bF);
                aG[p] = pk2(bG,bG); aO[p] = pk2(bO,bO);
            }

            // own k = 2j + kh, j = 0..43
            const ulonglong2* wr = wq + (size_t)(2*kh)*NUP + u;
            const float*      vp = vc + (base + kh)*VPF + cg*8;
            #pragma unroll 2
            for (int j = 0; j < 44; j++){
                ulonglong2 wa = wr[(size_t)j*4*NUP];        // (wi,wi),(wf,wf)
                ulonglong2 wb = wr[(size_t)j*4*NUP + NUP];  // (wg,wg),(wo,wo)
                ulonglong2 v0 = *reinterpret_cast<const ulonglong2*>(vp + j*2*VPF);
                ulonglong2 v1 = *reinterpret_cast<const ulonglong2*>(vp + j*2*VPF + 4);
                fma2(aI[0], wa.x, v0.x); fma2(aI[1], wa.x, v0.y);
                fma2(aI[2], wa.x, v1.x); fma2(aI[3], wa.x, v1.y);
                fma2(aF[0], wa.y, v0.x); fma2(aF[1], wa.y, v0.y);
                fma2(aF[2], wa.y, v1.x); fma2(aF[3], wa.y, v1.y);
                fma2(aG[0], wb.x, v0.x); fma2(aG[1], wb.x, v0.y);
                fma2(aG[2], wb.x, v1.x); fma2(aG[3], wb.x, v1.y);
                fma2(aO[0], wb.y, v0.x); fma2(aO[1], wb.y, v0.y);
                fma2(aO[2], wb.y, v1.x); fma2(aO[3], wb.y, v1.y);
            }

            // Combine k-halves UNCONDITIONALLY (deadlock fix: both pair lanes
            // always execute these shuffles, every iteration).
            #pragma unroll
            for (int p = 0; p < 4; p++){
                aI[p] = add2(aI[p], __shfl_xor_sync(pmask, aI[p], 1));
                aF[p] = add2(aF[p], __shfl_xor_sync(pmask, aF[p], 1));
                aG[p] = add2(aG[p], __shfl_xor_sync(pmask, aG[p], 1));
                aO[p] = add2(aO[p], __shfl_xor_sync(pmask, aO[p], 1));
            }

            if (isL1 ? (t < Tc) : (t >= 1)){
                int p0 = 2*kh, p1 = 2*kh + 1;
                float i0,i1,i2,i3, f0,f1,f2,f3, g0,g1,g2,g3, o0,o1,o2,o3;
                up2(aI[p0], i0, i1); up2(aI[p1], i2, i3);
                up2(aF[p0], f0, f1); up2(aF[p1], f2, f3);
                up2(aG[p0], g0, g1); up2(aG[p1], g2, g3);
                up2(aO[p0], o0, o1); up2(aO[p1], o2, o3);
                float c0 = fmaf(sigf(f0), cst[0], sigf(i0)*tanh_(g0));
                float c1 = fmaf(sigf(f1), cst[1], sigf(i1)*tanh_(g1));
                float c2 = fmaf(sigf(f2), cst[2], sigf(i2)*tanh_(g2));
                float c3 = fmaf(sigf(f3), cst[3], sigf(i3)*tanh_(g3));
                cst[0]=c0; cst[1]=c1; cst[2]=c2; cst[3]=c3;
                float4 hv;
                hv.x = sigf(o0)*tanh_(c0);
                hv.y = sigf(o1)*tanh_(c1);
                hv.z = sigf(o2)*tanh_(c2);
                hv.w = sigf(o3)*tanh_(c3);
                *reinterpret_cast<float4*>(vn + hrow*VPF + cg*8 + kh*4) = hv;
            }
        } else if (tid >= 544){
            // ---- Prefetch warp: coalesced load of x(t+1), staged transpose ----
            int lane = tid - 544;
            if (t + 1 < Tc){
                #pragma unroll 4
                for (int r = 0; r < NB; r++){
                    const float* xs = x + ((size_t)(b0 + r) * Tc + (t + 1)) * I1c;
                    stg[r*STAGE_PITCH + lane] = __ldcg(xs + lane);
                    if (lane < I1c - 32)
                        stg[r*STAGE_PITCH + 32 + lane] = __ldcg(xs + 32 + lane);
                }
                __syncwarp();
                #pragma unroll
                for (int i = 0; i < I1c; i++)
                    vn[i*VPF + lane] = stg[lane*STAGE_PITCH + i];
            }
        }
        __syncthreads();
    }

    // ---- FC head: final h2 in vbuf[1] rows 88..102 ----
    const float* h2f = vbuf + VSZ + 88*VPF;
    for (int q = tid; q < NB*NCc; q += NTH){
        int nb = q / NCc, cls = q % NCc;
        float s = b_fc[cls];
        #pragma unroll
        for (int h = 0; h < H2c; h++)
            s = fmaf(w_fc[cls*H2c + h], h2f[h*VPF + nb], s);
        out[(size_t)(b0 + nb)*NCc + cls] = s;
    }
}

extern "C" void kernel_launch(void* const* d_in, const int* in_sizes, int n_in,
                              void* d_out, int out_size)
{
    const float* x     = (const float*)d_in[0];
    const float* w_ih1 = (const float*)d_in[1];
    const float* w_hh1 = (const float*)d_in[2];
    const float* b_ih1 = (const float*)d_in[3];
    const float* b_hh1 = (const float*)d_in[4];
    const float* w_ih2 = (const float*)d_in[5];
    const float* w_hh2 = (const float*)d_in[6];
    const float* b_ih2 = (const float*)d_in[7];
    const float* b_hh2 = (const float*)d_in[8];
    const float* w_fc  = (const float*)d_in[9];
    const float* b_fc  = (const float*)d_in[10];
    float* out = (float*)d_out;

    cudaFuncSetAttribute(lstm_persist_kernel,
                         cudaFuncAttributeMaxDynamicSharedMemorySize, SMEM_BYTES);

    const int grid = Bc / NB;   // 128 CTAs -> one wave
    lstm_persist_kernel<<<grid, NTH, SMEM_BYTES>>>(
        x, w_ih1, w_hh1, b_ih1, b_hh1,
        w_ih2, w_hh2, b_ih2, b_hh2, w_fc, b_fc, out);
}